// round 15
// baseline (speedup 1.0000x reference)
#include <cuda_runtime.h>
#include <cuda_fp16.h>
#include <cstdint>

#define MCN     50000
#define PATHS   100000
#define TSTEPS  180
#define NOPT    32
#define BDIM    256
#define NT      782          /* ceil(100000/128) */
#define HSTEP   (1.0f/360.0f)
#define RATEC   0.025f

__device__ float g_part[NT * NOPT];

// ---- shared memory byte offsets ----
#define OFF_BSM2 0            // layer-2 B frags [net][kk][nn][lane] uint2 = 32768
#define OFF_BSM1 32768        // layer-1 B frags [net][j][lane] u32 = 4096
#define OFF_BW   36864        // 128 float4 = 2048 ({b2,b2,Wo,Wo})
#define OFF_STRK 38912        // 32 f
#define OFF_MASK 39040        // 180 u32 = 720
#define OFF_WSUM 39760        // 32*8 f = 1024
#define SMEM_TOTAL 40800

__device__ __forceinline__ uint32_t packh2(float lo, float hi) {
    __half2 h = __floats2half2_rn(lo, hi);
    return *(uint32_t*)&h;
}
__device__ __forceinline__ uint32_t hmax2z(uint32_t u) {
    __half2 zero = __float2half2_rn(0.0f);
    __half2 r = __hmax2(*(__half2*)&u, zero);
    return *(uint32_t*)&r;
}
__device__ __forceinline__ void mma_f16_k16(float c[4], const uint32_t a[4],
                                            uint32_t b0, uint32_t b1) {
    asm volatile("mma.sync.aligned.m16n8k16.row.col.f32.f16.f16.f32 "
                 "{%0,%1,%2,%3}, {%4,%5,%6,%7}, {%8,%9}, {%0,%1,%2,%3};"
                 : "+f"(c[0]), "+f"(c[1]), "+f"(c[2]), "+f"(c[3])
                 : "r"(a[0]), "r"(a[1]), "r"(a[2]), "r"(a[3]), "r"(b0), "r"(b1));
}
__device__ __forceinline__ void mma_f16_k8(float c[4], uint32_t a0, uint32_t a1,
                                           uint32_t b0) {
    asm volatile("mma.sync.aligned.m16n8k8.row.col.f32.f16.f16.f32 "
                 "{%0,%1,%2,%3}, {%4,%5}, {%6}, {%0,%1,%2,%3};"
                 : "+f"(c[0]), "+f"(c[1]), "+f"(c[2]), "+f"(c[3])
                 : "r"(a0), "r"(a1), "r"(b0));
}

__global__ __launch_bounds__(BDIM, 3)
void sde_mc_hmma_kernel(const float* __restrict__ x,
                        const float* __restrict__ z,
                        const float* __restrict__ z1,
                        const float* __restrict__ W1,
                        const float* __restrict__ b1,
                        const float* __restrict__ W2,
                        const float* __restrict__ b2,
                        const float* __restrict__ Wo,
                        const float* __restrict__ bo)
{
    extern __shared__ char sm[];
    const int tid  = threadIdx.x;
    const int wid  = tid >> 5;
    const int lane = tid & 31;
    const int g    = lane >> 2;      // fragment group row
    const int t4   = lane & 3;       // fragment thread-in-group

    uint2*  bsm2 = (uint2*)(sm + OFF_BSM2);
    uint32_t* bsm1 = (uint32_t*)(sm + OFF_BSM1);
    float4* bw4S = (float4*)(sm + OFF_BW);
    float*  strk = (float*)(sm + OFF_STRK);
    unsigned* maskS = (unsigned*)(sm + OFF_MASK);
    float*  wsum = (float*)(sm + OFF_WSUM);

    // ---- stage layer-2 B fragments: bsm2[((net*4+kk)*8+nn)*32+lane] ----
    for (int e = tid; e < 4096; e += BDIM) {
        int ln = e & 31, nn = (e >> 5) & 7, kk = (e >> 8) & 3, netI = e >> 10;
        int n = nn * 8 + (ln >> 2);
        int k = kk * 16 + 2 * (ln & 3);
        const float* Wn = W2 + netI * 4096 + n * 64;
        bsm2[e] = make_uint2(packh2(__ldg(Wn + k),     __ldg(Wn + k + 1)),
                             packh2(__ldg(Wn + k + 8), __ldg(Wn + k + 9)));
    }
    // ---- stage layer-1 B fragments: bsm1[(net*8+j)*32+lane] ----
    for (int e = tid; e < 1024; e += BDIM) {
        int ln = e & 31, j = (e >> 5) & 7, netI = e >> 8;
        int n = j * 8 + (ln >> 2), tt = ln & 3;
        const float* W1n = W1 + netI * 256;
        float lo, hi;
        if (tt == 0)      { lo = __ldg(W1n + n * 4 + 0); hi = __ldg(W1n + n * 4 + 1); }
        else if (tt == 1) { lo = __ldg(W1n + n * 4 + 2); hi = 0.0f; }
        else if (tt == 2) { lo = fmaf(RATEC, __ldg(W1n + n * 4 + 3), __ldg(b1 + netI * 64 + n)); hi = 0.0f; }
        else              { lo = 0.0f; hi = 0.0f; }
        bsm1[e] = packh2(lo, hi);
    }
    // ---- bw4[net*32+nn*4+t4] = {b2[c],b2[c+1],Wo[c],Wo[c+1]} ----
    if (tid < 128) {
        int netI = tid >> 5, rem = tid & 31, nn = rem >> 2, t4i = rem & 3;
        int c = netI * 64 + nn * 8 + 2 * t4i;
        bw4S[tid] = make_float4(__ldg(b2 + c), __ldg(b2 + c + 1),
                                __ldg(Wo + c), __ldg(Wo + c + 1));
    }
    if (tid < NOPT) strk[tid] = x[2 * tid + 1];
    for (int i = tid; i < TSTEPS; i += BDIM) {
        unsigned m = 0;
        for (int k = 0; k < NOPT; k++)
            if ((int)x[2 * k] == i + 1) m |= (1u << k);
        maskS[i] = m;
    }
    if (tid < NOPT * 8) wsum[tid] = 0.0f;
    __syncthreads();   // ONLY barrier before the final reduce

    // ---- per-warp path ownership: paths p0 = base+g, p1 = base+g+8 ----
    const int base = blockIdx.x * 128 + wid * 16;
    const int p0 = base + g, p1 = base + g + 8;
    const bool valid0 = p0 < PATHS, valid1 = p1 < PATHS;
    const int  zrow0 = (p0 < MCN) ? p0 : (valid0 ? p0 - MCN : 0);
    const int  zrow1 = (p1 < MCN) ? p1 : (valid1 ? p1 - MCN : 0);
    const float sgn0 = (p0 < MCN) ? 1.0f : -1.0f;
    const float sgn1 = (p1 < MCN) ? 1.0f : -1.0f;
    const float* zr0  = z  + (long)zrow0 * TSTEPS;
    const float* z1r0 = z1 + (long)zrow0 * TSTEPS;
    const float* zr1  = z  + (long)zrow1 * TSTEPS;
    const float* z1r1 = z1 + (long)zrow1 * TSTEPS;
    const float SQH  = sqrtf(HSTEP);
    const float SQ75 = 0.8660254037844386f;
    const float bo0 = __ldg(bo), bo1 = __ldg(bo + 1),
                bo2 = __ldg(bo + 2), bo3 = __ldg(bo + 3);

    float S0 = 100.0f, V0 = 0.04f, S1 = 100.0f, V1 = 0.04f;
    const uint32_t one_h = 0x00003C00u;   // packh2(1.0, 0.0)

    for (int i = 0; i < TSTEPS; i++) {
        // z prefetch (all lanes of a quad load same addr -> 1 sector)
        float za0 = __ldg(zr0 + i), zb0 = __ldg(z1r0 + i);
        float za1 = __ldg(zr1 + i), zb1 = __ldg(z1r1 + i);

        const float th = (float)i * HSTEP;
        // A fragments: X = [t,S,V,0,1,0,0,0]; S,V correct on ALL lanes
        uint32_t a0 = (t4 == 0) ? packh2(th, S0)
                    : (t4 == 1) ? packh2(V0, 0.0f)
                    : (t4 == 2) ? one_h : 0u;
        uint32_t a1 = (t4 == 0) ? packh2(th, S1)
                    : (t4 == 1) ? packh2(V1, 0.0f)
                    : (t4 == 2) ? one_h : 0u;

        float dS0 = 0.f, dS1 = 0.f, dV0 = 0.f, dV1 = 0.f;

        #pragma unroll 1
        for (int net = 0; net < 4; net++) {
            // layer 1: 8 k8 MMAs, B from bsm1
            uint32_t a[4][4];
            const uint32_t* w1n = bsm1 + net * 256 + lane;
            #pragma unroll
            for (int kk = 0; kk < 4; kk++) {
                #pragma unroll
                for (int jh = 0; jh < 2; jh++) {
                    int j = 2 * kk + jh;
                    float d[4] = {0.f, 0.f, 0.f, 0.f};
                    mma_f16_k8(d, a0, a1, w1n[j * 32]);
                    a[kk][2 * jh]     = hmax2z(packh2(d[0], d[1]));
                    a[kk][2 * jh + 1] = hmax2z(packh2(d[2], d[3]));
                }
            }
            // layer 2: 32 k16 MMAs, B from bsm2; epilogue fused
            float op0 = 0.f, op1 = 0.f;
            const uint2* b2n = bsm2 + net * 1024 + lane;
            #pragma unroll
            for (int nn = 0; nn < 8; nn++) {
                float4 bw = bw4S[net * 32 + nn * 4 + t4];
                float acc[4] = {bw.x, bw.y, bw.x, bw.y};
                #pragma unroll
                for (int kk = 0; kk < 4; kk++) {
                    uint2 b = b2n[(kk * 8 + nn) * 32];
                    mma_f16_k16(acc, a[kk], b.x, b.y);
                }
                float q0 = fmaxf(acc[0], 0.f);
                float q1 = fmaxf(acc[1], 0.f);
                float q2 = fmaxf(acc[2], 0.f);
                float q3 = fmaxf(acc[3], 0.f);
                op0 = fmaf(bw.z, q0, fmaf(bw.w, q1, op0));
                op1 = fmaf(bw.z, q2, fmaf(bw.w, q3, op1));
            }
            // butterfly: ALL 4 quad lanes end with the full sum
            op0 += __shfl_xor_sync(0xffffffffu, op0, 1);
            op0 += __shfl_xor_sync(0xffffffffu, op0, 2);
            op1 += __shfl_xor_sync(0xffffffffu, op1, 1);
            op1 += __shfl_xor_sync(0xffffffffu, op1, 2);

            if (net == 0) { dS0 = (op0 + bo0) * HSTEP; dS1 = (op1 + bo0) * HSTEP; }
            else if (net == 1) {
                float dW0 = SQH * sgn0 * za0, dW1w = SQH * sgn1 * za1;
                dS0 = fmaf(op0 + bo1, dW0,  dS0);
                dS1 = fmaf(op1 + bo1, dW1w, dS1);
            }
            else if (net == 2) { dV0 = (op0 + bo2) * HSTEP; dV1 = (op1 + bo2) * HSTEP; }
            else {
                float dB0 = SQH * sgn0 * fmaf(SQ75, zb0, -0.5f * za0);
                float dB1 = SQH * sgn1 * fmaf(SQ75, zb1, -0.5f * za1);
                dV0 = fmaf(op0 + bo3, dB0, dV0);
                dV1 = fmaf(op1 + bo3, dB1, dV1);
            }
        }

        // Euler update + clamp (correct on all lanes)
        S0 = fmaxf(S0 + dS0, 0.0f);
        V0 = fmaxf(V0 + dV0, 0.0f);
        S1 = fmaxf(S1 + dS1, 0.0f);
        V1 = fmaxf(V1 + dV1, 0.0f);

        // payoff events (t4==0 lanes contribute; full-warp reduce)
        unsigned m = maskS[i];
        while (m) {
            int k = __ffs(m) - 1; m &= m - 1;
            float K = strk[k];
            float pay = 0.0f;
            if (t4 == 0) {
                if (valid0) pay += fmaxf(S0 - K, 0.0f);
                if (valid1) pay += fmaxf(S1 - K, 0.0f);
            }
            #pragma unroll
            for (int off = 16; off; off >>= 1)
                pay += __shfl_down_sync(0xffffffffu, pay, off);
            if (lane == 0) wsum[k * 8 + wid] = pay;
        }
    }

    __syncthreads();
    if (tid < NOPT) {
        float s = 0.f;
        #pragma unroll
        for (int w = 0; w < 8; w++) s += wsum[tid * 8 + w];
        g_part[blockIdx.x * NOPT + tid] = s;
    }
}

// ---------------- finalize: one warp per option ----------------
__global__ void finalize_kernel(const float* __restrict__ x, float* __restrict__ out)
{
    int k = threadIdx.x >> 5, lane = threadIdx.x & 31;
    float s = 0.0f;
    for (int t = lane; t < NT; t += 32) s += g_part[t * NOPT + k];
    #pragma unroll
    for (int off = 16; off; off >>= 1) s += __shfl_down_sync(0xffffffffu, s, off);
    if (lane == 0)
        out[k] = (s * (1.0f / (2.0f * (float)MCN))) * expf(-RATEC * x[2 * k] / 360.0f);
}

__global__ void dummy_kernel() {}

extern "C" void kernel_launch(void* const* d_in, const int* in_sizes, int n_in,
                              void* d_out, int out_size)
{
    (void)in_sizes; (void)n_in; (void)out_size;
    const float* x  = (const float*)d_in[0];
    const float* z  = (const float*)d_in[1];
    const float* z1 = (const float*)d_in[2];
    const float* W1 = (const float*)d_in[3];
    const float* b1 = (const float*)d_in[4];
    const float* W2 = (const float*)d_in[5];
    const float* b2 = (const float*)d_in[6];
    const float* Wo = (const float*)d_in[7];
    const float* bo = (const float*)d_in[8];

    cudaFuncSetAttribute(sde_mc_hmma_kernel,
                         cudaFuncAttributeMaxDynamicSharedMemorySize, SMEM_TOTAL);
    dummy_kernel<<<1, 32>>>();
    dummy_kernel<<<1, 32>>>();
    dummy_kernel<<<1, 32>>>();
    sde_mc_hmma_kernel<<<NT, BDIM, SMEM_TOTAL>>>(x, z, z1, W1, b1, W2, b2, Wo, bo);
    finalize_kernel<<<1, 1024>>>(x, (float*)d_out);
}

// round 16
// speedup vs baseline: 1.0524x; 1.0524x over previous
#include <cuda_runtime.h>
#include <cuda_fp16.h>
#include <cstdint>

#define MCN     50000
#define PATHS   100000
#define TSTEPS  180
#define NOPT    32
#define BDIM    128
#define NT      782          /* ceil(100000/128) */
#define HSTEP   (1.0f/360.0f)
#define RATEC   0.025f

__device__ float g_part[NT * NOPT];

// ---- shared memory byte offsets ----
#define OFF_BSM2 0            // layer-2 B frags [net][kk][nn][lane] uint2 = 32768
#define OFF_BSM1 32768        // layer-1 B frags [net][j][lane] u32 = 4096
#define OFF_BW   36864        // 128 float4 = 2048 ({b2,b2,Wo,Wo})
#define OFF_STRK 38912        // 32 f
#define OFF_MASK 39040        // 180 u32 = 720
#define OFF_WSUM 39760        // 32*4 f = 512
#define SMEM_TOTAL 40288

__device__ __forceinline__ uint32_t packh2(float lo, float hi) {
    __half2 h = __floats2half2_rn(lo, hi);
    return *(uint32_t*)&h;
}
__device__ __forceinline__ uint32_t hmax2z(uint32_t u) {
    __half2 zero = __float2half2_rn(0.0f);
    __half2 r = __hmax2(*(__half2*)&u, zero);
    return *(uint32_t*)&r;
}
__device__ __forceinline__ void mma_f16_k16(float c[4], const uint32_t a[4],
                                            uint32_t b0, uint32_t b1) {
    asm volatile("mma.sync.aligned.m16n8k16.row.col.f32.f16.f16.f32 "
                 "{%0,%1,%2,%3}, {%4,%5,%6,%7}, {%8,%9}, {%0,%1,%2,%3};"
                 : "+f"(c[0]), "+f"(c[1]), "+f"(c[2]), "+f"(c[3])
                 : "r"(a[0]), "r"(a[1]), "r"(a[2]), "r"(a[3]), "r"(b0), "r"(b1));
}
__device__ __forceinline__ void mma_f16_k8(float c[4], uint32_t a0, uint32_t a1,
                                           uint32_t b0) {
    asm volatile("mma.sync.aligned.m16n8k8.row.col.f32.f16.f16.f32 "
                 "{%0,%1,%2,%3}, {%4,%5}, {%6}, {%0,%1,%2,%3};"
                 : "+f"(c[0]), "+f"(c[1]), "+f"(c[2]), "+f"(c[3])
                 : "r"(a0), "r"(a1), "r"(b0));
}

__global__ __launch_bounds__(BDIM, 4)
void sde_mc_hmma_kernel(const float* __restrict__ x,
                        const float* __restrict__ z,
                        const float* __restrict__ z1,
                        const float* __restrict__ W1,
                        const float* __restrict__ b1,
                        const float* __restrict__ W2,
                        const float* __restrict__ b2,
                        const float* __restrict__ Wo,
                        const float* __restrict__ bo)
{
    extern __shared__ char sm[];
    const int tid  = threadIdx.x;
    const int wid  = tid >> 5;       // 4 warps; warp owns 32 paths
    const int lane = tid & 31;
    const int g    = lane >> 2;      // fragment group row
    const int t4   = lane & 3;       // fragment thread-in-group

    uint2*    bsm2 = (uint2*)(sm + OFF_BSM2);
    uint32_t* bsm1 = (uint32_t*)(sm + OFF_BSM1);
    float4*   bw4S = (float4*)(sm + OFF_BW);
    float*    strk = (float*)(sm + OFF_STRK);
    unsigned* maskS = (unsigned*)(sm + OFF_MASK);
    float*    wsum = (float*)(sm + OFF_WSUM);

    // ---- stage layer-2 B fragments: bsm2[((net*4+kk)*8+nn)*32+lane] ----
    for (int e = tid; e < 4096; e += BDIM) {
        int ln = e & 31, nn = (e >> 5) & 7, kk = (e >> 8) & 3, netI = e >> 10;
        int n = nn * 8 + (ln >> 2);
        int k = kk * 16 + 2 * (ln & 3);
        const float* Wn = W2 + netI * 4096 + n * 64;
        bsm2[e] = make_uint2(packh2(__ldg(Wn + k),     __ldg(Wn + k + 1)),
                             packh2(__ldg(Wn + k + 8), __ldg(Wn + k + 9)));
    }
    // ---- stage layer-1 B fragments: bsm1[(net*8+j)*32+lane] ----
    for (int e = tid; e < 1024; e += BDIM) {
        int ln = e & 31, j = (e >> 5) & 7, netI = e >> 8;
        int n = j * 8 + (ln >> 2), tt = ln & 3;
        const float* W1n = W1 + netI * 256;
        float lo, hi;
        if (tt == 0)      { lo = __ldg(W1n + n * 4 + 0); hi = __ldg(W1n + n * 4 + 1); }
        else if (tt == 1) { lo = __ldg(W1n + n * 4 + 2); hi = 0.0f; }
        else if (tt == 2) { lo = fmaf(RATEC, __ldg(W1n + n * 4 + 3), __ldg(b1 + netI * 64 + n)); hi = 0.0f; }
        else              { lo = 0.0f; hi = 0.0f; }
        bsm1[e] = packh2(lo, hi);
    }
    // ---- bw4[net*32+nn*4+t4] = {b2[c],b2[c+1],Wo[c],Wo[c+1]} ----
    {
        int netI = tid >> 5, rem = tid & 31, nn = rem >> 2, t4i = rem & 3;
        int c = netI * 64 + nn * 8 + 2 * t4i;
        bw4S[tid] = make_float4(__ldg(b2 + c), __ldg(b2 + c + 1),
                                __ldg(Wo + c), __ldg(Wo + c + 1));
    }
    if (tid < NOPT) strk[tid] = x[2 * tid + 1];
    for (int i = tid; i < TSTEPS; i += BDIM) {
        unsigned m = 0;
        for (int k = 0; k < NOPT; k++)
            if ((int)x[2 * k] == i + 1) m |= (1u << k);
        maskS[i] = m;
    }
    if (tid < NOPT * 4) wsum[tid] = 0.0f;
    __syncthreads();   // ONLY barrier before the final reduce

    // ---- per-warp ownership: 32 paths, rows g+8j (j=0..3) ----
    const int base = blockIdx.x * 128 + wid * 32;
    int   zo[4];
    float sgn[4];
    bool  vld[4];
    #pragma unroll
    for (int j = 0; j < 4; j++) {
        int p = base + g + 8 * j;
        vld[j] = p < PATHS;
        int zrow = (p < MCN) ? p : (vld[j] ? p - MCN : 0);
        zo[j]  = zrow * TSTEPS;
        sgn[j] = (p < MCN) ? 1.0f : -1.0f;
    }
    const float SQH  = sqrtf(HSTEP);
    const float SQ75 = 0.8660254037844386f;
    const float bo0 = __ldg(bo), bo1 = __ldg(bo + 1),
                bo2 = __ldg(bo + 2), bo3 = __ldg(bo + 3);

    float S[4] = {100.0f, 100.0f, 100.0f, 100.0f};
    float V[4] = {0.04f, 0.04f, 0.04f, 0.04f};
    const uint32_t one_h = 0x00003C00u;   // packh2(1.0, 0.0)

    for (int i = 0; i < TSTEPS; i++) {
        float za[4], zb[4];
        #pragma unroll
        for (int j = 0; j < 4; j++) {
            za[j] = __ldg(z  + zo[j] + i);
            zb[j] = __ldg(z1 + zo[j] + i);
        }
        const float th = (float)i * HSTEP;
        // A k8 fragments: X = [t,S,V,0,1,0,0,0]; tile0 rows g/g+8, tile1 rows g+16/g+24
        uint32_t aA0 = (t4 == 0) ? packh2(th, S[0]) : (t4 == 1) ? packh2(V[0], 0.f)
                     : (t4 == 2) ? one_h : 0u;
        uint32_t aA1 = (t4 == 0) ? packh2(th, S[1]) : (t4 == 1) ? packh2(V[1], 0.f)
                     : (t4 == 2) ? one_h : 0u;
        uint32_t aB0 = (t4 == 0) ? packh2(th, S[2]) : (t4 == 1) ? packh2(V[2], 0.f)
                     : (t4 == 2) ? one_h : 0u;
        uint32_t aB1 = (t4 == 0) ? packh2(th, S[3]) : (t4 == 1) ? packh2(V[3], 0.f)
                     : (t4 == 2) ? one_h : 0u;

        float dS[4] = {0.f, 0.f, 0.f, 0.f};
        float dV[4] = {0.f, 0.f, 0.f, 0.f};

        #pragma unroll 1
        for (int net = 0; net < 4; net++) {
            // layer 1: 8 B-frags loaded once, used for both tiles (16 k8 MMAs)
            uint32_t a[4][4], b[4][4];
            const uint32_t* w1n = bsm1 + net * 256 + lane;
            #pragma unroll
            for (int kk = 0; kk < 4; kk++) {
                #pragma unroll
                for (int jh = 0; jh < 2; jh++) {
                    uint32_t wb = w1n[(2 * kk + jh) * 32];
                    float d0[4] = {0.f, 0.f, 0.f, 0.f};
                    mma_f16_k8(d0, aA0, aA1, wb);
                    a[kk][2 * jh]     = hmax2z(packh2(d0[0], d0[1]));
                    a[kk][2 * jh + 1] = hmax2z(packh2(d0[2], d0[3]));
                    float d1[4] = {0.f, 0.f, 0.f, 0.f};
                    mma_f16_k8(d1, aB0, aB1, wb);
                    b[kk][2 * jh]     = hmax2z(packh2(d1[0], d1[1]));
                    b[kk][2 * jh + 1] = hmax2z(packh2(d1[2], d1[3]));
                }
            }
            // layer 2: B loaded once per (kk,nn), 2 MMAs each (64 k16 MMAs)
            float op0 = 0.f, op1 = 0.f, op2 = 0.f, op3 = 0.f;
            const uint2* b2n = bsm2 + net * 1024 + lane;
            #pragma unroll
            for (int nn = 0; nn < 8; nn++) {
                float4 bw = bw4S[net * 32 + nn * 4 + t4];
                float accA[4] = {bw.x, bw.y, bw.x, bw.y};
                float accB[4] = {bw.x, bw.y, bw.x, bw.y};
                #pragma unroll
                for (int kk = 0; kk < 4; kk++) {
                    uint2 bb = b2n[(kk * 8 + nn) * 32];
                    mma_f16_k16(accA, a[kk], bb.x, bb.y);
                    mma_f16_k16(accB, b[kk], bb.x, bb.y);
                }
                op0 = fmaf(bw.z, fmaxf(accA[0], 0.f), fmaf(bw.w, fmaxf(accA[1], 0.f), op0));
                op1 = fmaf(bw.z, fmaxf(accA[2], 0.f), fmaf(bw.w, fmaxf(accA[3], 0.f), op1));
                op2 = fmaf(bw.z, fmaxf(accB[0], 0.f), fmaf(bw.w, fmaxf(accB[1], 0.f), op2));
                op3 = fmaf(bw.z, fmaxf(accB[2], 0.f), fmaf(bw.w, fmaxf(accB[3], 0.f), op3));
            }
            op0 += __shfl_xor_sync(0xffffffffu, op0, 1);
            op0 += __shfl_xor_sync(0xffffffffu, op0, 2);
            op1 += __shfl_xor_sync(0xffffffffu, op1, 1);
            op1 += __shfl_xor_sync(0xffffffffu, op1, 2);
            op2 += __shfl_xor_sync(0xffffffffu, op2, 1);
            op2 += __shfl_xor_sync(0xffffffffu, op2, 2);
            op3 += __shfl_xor_sync(0xffffffffu, op3, 1);
            op3 += __shfl_xor_sync(0xffffffffu, op3, 2);
            float op[4] = {op0, op1, op2, op3};

            if (net == 0) {
                #pragma unroll
                for (int j = 0; j < 4; j++) dS[j] = (op[j] + bo0) * HSTEP;
            } else if (net == 1) {
                #pragma unroll
                for (int j = 0; j < 4; j++)
                    dS[j] = fmaf(op[j] + bo1, SQH * sgn[j] * za[j], dS[j]);
            } else if (net == 2) {
                #pragma unroll
                for (int j = 0; j < 4; j++) dV[j] = (op[j] + bo2) * HSTEP;
            } else {
                #pragma unroll
                for (int j = 0; j < 4; j++) {
                    float dB = SQH * sgn[j] * fmaf(SQ75, zb[j], -0.5f * za[j]);
                    dV[j] = fmaf(op[j] + bo3, dB, dV[j]);
                }
            }
        }

        // Euler update + clamp (correct on all lanes)
        #pragma unroll
        for (int j = 0; j < 4; j++) {
            S[j] = fmaxf(S[j] + dS[j], 0.0f);
            V[j] = fmaxf(V[j] + dV[j], 0.0f);
        }

        // payoff events (t4==0 lanes contribute their 4 paths)
        unsigned m = maskS[i];
        while (m) {
            int k = __ffs(m) - 1; m &= m - 1;
            float K = strk[k];
            float pay = 0.0f;
            if (t4 == 0) {
                #pragma unroll
                for (int j = 0; j < 4; j++)
                    if (vld[j]) pay += fmaxf(S[j] - K, 0.0f);
            }
            #pragma unroll
            for (int off = 16; off; off >>= 1)
                pay += __shfl_down_sync(0xffffffffu, pay, off);
            if (lane == 0) wsum[k * 4 + wid] = pay;
        }
    }

    __syncthreads();
    if (tid < NOPT) {
        float s = wsum[tid * 4] + wsum[tid * 4 + 1]
                + wsum[tid * 4 + 2] + wsum[tid * 4 + 3];
        g_part[blockIdx.x * NOPT + tid] = s;
    }
}

// ---------------- finalize: one warp per option ----------------
__global__ void finalize_kernel(const float* __restrict__ x, float* __restrict__ out)
{
    int k = threadIdx.x >> 5, lane = threadIdx.x & 31;
    float s = 0.0f;
    for (int t = lane; t < NT; t += 32) s += g_part[t * NOPT + k];
    #pragma unroll
    for (int off = 16; off; off >>= 1) s += __shfl_down_sync(0xffffffffu, s, off);
    if (lane == 0)
        out[k] = (s * (1.0f / (2.0f * (float)MCN))) * expf(-RATEC * x[2 * k] / 360.0f);
}

__global__ void dummy_kernel() {}

extern "C" void kernel_launch(void* const* d_in, const int* in_sizes, int n_in,
                              void* d_out, int out_size)
{
    (void)in_sizes; (void)n_in; (void)out_size;
    const float* x  = (const float*)d_in[0];
    const float* z  = (const float*)d_in[1];
    const float* z1 = (const float*)d_in[2];
    const float* W1 = (const float*)d_in[3];
    const float* b1 = (const float*)d_in[4];
    const float* W2 = (const float*)d_in[5];
    const float* b2 = (const float*)d_in[6];
    const float* Wo = (const float*)d_in[7];
    const float* bo = (const float*)d_in[8];

    cudaFuncSetAttribute(sde_mc_hmma_kernel,
                         cudaFuncAttributeMaxDynamicSharedMemorySize, SMEM_TOTAL);
    dummy_kernel<<<1, 32>>>();
    dummy_kernel<<<1, 32>>>();
    dummy_kernel<<<1, 32>>>();
    sde_mc_hmma_kernel<<<NT, BDIM, SMEM_TOTAL>>>(x, z, z1, W1, b1, W2, b2, Wo, bo);
    finalize_kernel<<<1, 1024>>>(x, (float*)d_out);
}